// round 15
// baseline (speedup 1.0000x reference)
#include <cuda_runtime.h>
#include <cuda_fp16.h>
#include <cstdint>

// Shapes (fixed)
#define NB 4
#define NG 4096
#define DZ 128
#define NT 2048

// Tiling
#define MT 32              // t rows per CTA (2 warps x 16 rows)
#define GC 64              // g per chunk
#define NCHUNK (NG/GC)     // 64
#define ZROW 132           // u32 stride per g-pair row
#define TILE_U32 4608      // 32*ZROW(4224) + gmeta 256 + bbox 64 + pad
#define TILE_BYTES (TILE_U32*4)     // 18432 = 64thr*18*16B
#define NTHREADS 64        // 2 warps: mh 0/1 (full z, full g, both kk per warp)
#define PTHREADS 256
#define RT 512
#define SKIP_THR (-16.0f)  // exp2 arg threshold: w < 1.6e-5 -> negligible

typedef unsigned int u32;

__device__ __align__(16) u32 g_Zh[(size_t)NB * NCHUNK * TILE_U32];
__device__ int g_rankp[NB][2][8][4096];   // per-part partial ranks (plain stores)
__device__ u32 g_perm_t[NB][NT];
__device__ u32 g_perm_g[NB][NG];

__device__ __forceinline__ float ex2f(float x) {
    float y; asm("ex2.approx.f32 %0, %1;" : "=f"(y) : "f"(x)); return y;
}
__device__ __forceinline__ u32 f16x2(float lo, float hi) {
    u32 d; asm("cvt.rn.f16x2.f32 %0, %1, %2;" : "=r"(d) : "f"(hi), "f"(lo)); return d;
}
__device__ __forceinline__ u32 smem_u32(const void* p) {
    u32 a;
    asm("{ .reg .u64 t; cvta.to.shared.u64 t, %1; cvt.u32.u64 %0, t; }" : "=r"(a) : "l"(p));
    return a;
}
__device__ __forceinline__ void mma16816(float* c, u32 a0, u32 a1, u32 a2, u32 a3,
                                         u32 b0, u32 b1) {
    asm("mma.sync.aligned.m16n8k16.row.col.f32.f16.f16.f32 "
        "{%0,%1,%2,%3}, {%4,%5,%6,%7}, {%8,%9}, {%0,%1,%2,%3};"
        : "+f"(c[0]), "+f"(c[1]), "+f"(c[2]), "+f"(c[3])
        : "r"(a0), "r"(a1), "r"(a2), "r"(a3), "r"(b0), "r"(b1));
}
__device__ __forceinline__ u32 part1by1(u32 x) {
    x &= 0xFFFF;
    x = (x | (x << 8)) & 0x00FF00FF;
    x = (x | (x << 4)) & 0x0F0F0F0F;
    x = (x | (x << 2)) & 0x33333333;
    x = (x | (x << 1)) & 0x55555555;
    return x;
}
__device__ __forceinline__ u32 mcode(float2 v) {
    int mx = min(31, max(0, (int)(v.x * 32.f)));
    int my = min(31, max(0, (int)(v.y * 32.f)));
    return (part1by1((u32)mx) | (part1by1((u32)my) << 1)) & 0x3FF;
}
__device__ __forceinline__ void softplus_cc(const float* lsp, int kk, float& c0, float& c1) {
    const float HL2E = 0.7213475204444817f;
    float p0 = lsp[0 * 2 + kk], p1 = lsp[1 * 2 + kk];
    float sp0 = (p0 > 20.f) ? p0 : log1pf(expf(p0));
    float sp1 = (p1 > 20.f) ? p1 : log1pf(expf(p1));
    float i0 = 1.f / (1e-5f + sp0), i1 = 1.f / (1e-5f + sp1);
    c0 = -HL2E * i0 * i0;
    c1 = -HL2E * i1 * i1;
}

// ------- kernel 0: partial ranks (plain stores, no memset) -------------------
__global__ void __launch_bounds__(RT)
rank_pts(const float* __restrict__ xt_all, const float* __restrict__ xg_all)
{
    __shared__ __align__(16) u32 keys[RT];
    const int blk = blockIdx.x;
    const int b   = blk / 80;
    const int q   = blk % 80;
    const bool isG = q >= 16;
    int si, pj;
    const float2* src;
    if (isG) { int qq = q - 16; si = qq >> 3; pj = qq & 7;
               src = (const float2*)xg_all + (size_t)b * NG; }
    else     { si = q >> 2; pj = q & 3;
               src = (const float2*)xt_all + (size_t)b * NT; }
    const int tid = threadIdx.x;

    const int myi = si * RT + tid;
    const u32 myk = (mcode(src[myi]) << 12) | (u32)myi;
    const int pi  = pj * RT + tid;
    keys[tid] = (mcode(src[pi]) << 12) | (u32)pi;
    __syncthreads();

    int cnt = 0;
    const uint4* k4 = (const uint4*)keys;
#pragma unroll 16
    for (int j = 0; j < RT / 4; ++j) {
        uint4 kv = k4[j];
        cnt += (kv.x < myk) + (kv.y < myk) + (kv.z < myk) + (kv.w < myk);
    }
    g_rankp[b][isG ? 1 : 0][pj][myi] = cnt;
}

// ------- kernel 0b: sum partials, invert rank -> permutation ------------------
__global__ void __launch_bounds__(RT)
scatter_perm()
{
    const int i = blockIdx.x * RT + threadIdx.x;    // 0..NB*6144-1
    const int b = i / 6144;
    const int s = i % 6144;
    if (s < NT) {
        int rank = 0;
#pragma unroll
        for (int p = 0; p < 4; ++p) rank += g_rankp[b][0][p][s];
        g_perm_t[b][rank] = (u32)s;
    } else {
        int gi = s - NT;
        int rank = 0;
#pragma unroll
        for (int p = 0; p < 8; ++p) rank += g_rankp[b][1][p][gi];
        g_perm_g[b][rank] = (u32)gi;
    }
}

// ---------------- kernel 1: pack sorted tiles + gmeta + per-16g bbox ----------
__global__ void __launch_bounds__(PTHREADS)
prep_tiles(const float* __restrict__ zg_all, const float* __restrict__ xg_all,
           const float* __restrict__ lsp)
{
    __shared__ float sx[GC], sy[GC];
    const int bc  = blockIdx.x;
    const int b   = bc >> 6;
    const int gc  = bc & 63;
    const int tid = threadIdx.x;
    const int w   = tid >> 5;
    const int z4  = tid & 31;

    u32* tile = g_Zh + (size_t)bc * TILE_U32;
    const u32* pg = g_perm_g[b] + gc * GC;

#pragma unroll
    for (int it = 0; it < 4; ++it) {
        int gp = w + it * 8;
        u32 r0 = pg[2 * gp], r1 = pg[2 * gp + 1];
        float4 v0 = __ldg((const float4*)(zg_all + ((size_t)b * NG + r0) * DZ) + z4);
        float4 v1 = __ldg((const float4*)(zg_all + ((size_t)b * NG + r1) * DZ) + z4);
        u32* dst = tile + gp * ZROW;
        int p0 = (z4 & 1) * 64 + (z4 >> 1);
        dst[p0]      = f16x2(v0.x, v1.x);
        dst[p0 + 16] = f16x2(v0.y, v1.y);
        dst[p0 + 32] = f16x2(v0.z, v1.z);
        dst[p0 + 48] = f16x2(v0.w, v1.w);
    }

    if (tid < GC) {
        float c00, c01, c10, c11;
        softplus_cc(lsp, 0, c00, c01);
        softplus_cc(lsp, 1, c10, c11);
        u32 pgi = pg[tid];
        float2 xgv = __ldg((const float2*)xg_all + (size_t)b * NG + pgi);
        float s0 = xgv.x * xgv.x, s1 = xgv.y * xgv.y;
        float Bg0 = fmaf(s0, c00, s1 * c01);
        float Bg1 = fmaf(s0, c10, s1 * c11);
        ((float4*)(tile + 32 * ZROW))[tid] = make_float4(xgv.x, xgv.y, Bg0, Bg1);
        sx[tid] = xgv.x; sy[tid] = xgv.y;
    }
    __syncthreads();
    if (tid < 4) {   // bbox per 16-g slice
        float mnx = 1e30f, mxx = -1e30f, mny = 1e30f, mxy = -1e30f;
        for (int i = tid * 16; i < tid * 16 + 16; ++i) {
            mnx = fminf(mnx, sx[i]); mxx = fmaxf(mxx, sx[i]);
            mny = fminf(mny, sy[i]); mxy = fmaxf(mxy, sy[i]);
        }
        ((float4*)(tile + 32 * ZROW + 256))[tid] = make_float4(mnx, mxx, mny, mxy);
    }
}

// -------- A-fragment builder: one 16-g subslice, one kk, rows q/q+8 -----------
__device__ __forceinline__ void build_a(
    const float4* m, int kk,
    const float (&At)[2][2], const float (&u0)[2][2], const float (&u1)[2][2],
    u32 (&a)[4])
{
    float wvA[4], wvB[4];
#pragma unroll
    for (int i = 0; i < 4; ++i) {
        float Bv = kk ? m[i].w : m[i].z;
        wvA[i] = ex2f(fmaf(m[i].x, u0[0][kk], fmaf(m[i].y, u1[0][kk], Bv)) + At[0][kk]);
        wvB[i] = ex2f(fmaf(m[i].x, u0[1][kk], fmaf(m[i].y, u1[1][kk], Bv)) + At[1][kk]);
    }
    a[0] = f16x2(wvA[0], wvA[1]);
    a[1] = f16x2(wvB[0], wvB[1]);
    a[2] = f16x2(wvA[2], wvA[3]);
    a[3] = f16x2(wvB[2], wvB[3]);
}

// -------- one 16-g subslice, full z (16 j), both kk (branch-wrapped) ----------
__device__ __forceinline__ void do_sub(
    const u32* bu, const float4* gm, bool sk0, bool sk1,
    const float (&At)[2][2], const float (&u0)[2][2], const float (&u1)[2][2],
    float (&c)[2][16][4])
{
    if (sk0 && sk1) return;
    const uint4* bup = (const uint4*)bu;
    const uint4* blp = bup + ZROW;    // +4*ZROW u32 -> k cols 2r+8, 2r+9
    uint4 BU[4], BL[4];
#pragma unroll
    for (int m = 0; m < 4; ++m) { BU[m] = bup[m]; BL[m] = blp[m]; }
    float4 n[4] = { gm[0], gm[1], gm[8], gm[9] };

    if (!sk1) {
        u32 a[4];
        build_a(n, 1, At, u0, u1, a);
#pragma unroll
        for (int j = 0; j < 16; ++j)
            mma16816(c[1][j], a[0], a[1], a[2], a[3],
                     ((const u32*)BU)[j], ((const u32*)BL)[j]);
    }
    if (!sk0) {
        u32 a[4];
        build_a(n, 0, At, u0, u1, a);
#pragma unroll
        for (int j = 0; j < 16; ++j)
            mma16816(c[0][j], a[0], a[1], a[2], a[3],
                     ((const u32*)BU)[j], ((const u32*)BL)[j]);
    }
}

// ---------------- kernel 2: main ---------------------------------------------
__global__ void __launch_bounds__(NTHREADS, 4)
setconv_h(const float* __restrict__ xt_all,
          const float* __restrict__ lsp,
          float* __restrict__ out_all)
{
    __shared__ __align__(16) u32 smem[2 * TILE_U32];   // 36864 B

    const int cta  = blockIdx.x;        // 256 CTAs
    const int b    = cta >> 6;
    const int t0   = (cta & 63) * MT;   // sorted-t block
    const int tid  = threadIdx.x;
    const int mh   = tid >> 5;          // warp = t-half (16 rows)
    const int lane = tid & 31;
    const int q    = lane >> 2;
    const int r    = lane & 3;

    const u32 sbase = smem_u32(smem);
    const char* gtiles = (const char*)(g_Zh + (size_t)b * NCHUNK * TILE_U32);

    float cck[2][2];
    softplus_cc(lsp, 0, cck[0][0], cck[0][1]);
    softplus_cc(lsp, 1, cck[1][0], cck[1][1]);

    // stage sorted t positions + original indices
    float2* xts = (float2*)smem;
    u32*    xti = (u32*)smem + 64;
    if (tid < MT) {
        u32 p = g_perm_t[b][t0 + tid];
        xti[tid] = p;
        xts[tid] = ((const float2*)xt_all)[(size_t)b * NT + p];
    }
    __syncthreads();

    // per-warp t-bbox (16 adjacent sorted rows)
    float tmnx = 1e30f, tmxx = -1e30f, tmny = 1e30f, tmxy = -1e30f;
#pragma unroll
    for (int i = 0; i < 16; ++i) {
        float2 v = xts[mh * 16 + i];
        tmnx = fminf(tmnx, v.x); tmxx = fmaxf(tmxx, v.x);
        tmny = fminf(tmny, v.y); tmxy = fmaxf(tmxy, v.y);
    }
    const int rowA = mh * 16 + q, rowB = rowA + 8;
    const float2 xvA = xts[rowA], xvB = xts[rowB];
    const u32 pA = xti[rowA], pB = xti[rowB];
    __syncthreads();

    float At[2][2], u0[2][2], u1[2][2];   // [row A/B][kk]
#pragma unroll
    for (int kk = 0; kk < 2; ++kk) {
        At[0][kk] = fmaf(xvA.x * xvA.x, cck[kk][0], xvA.y * xvA.y * cck[kk][1]);
        u0[0][kk] = -2.f * cck[kk][0] * xvA.x;
        u1[0][kk] = -2.f * cck[kk][1] * xvA.y;
        At[1][kk] = fmaf(xvB.x * xvB.x, cck[kk][0], xvB.y * xvB.y * cck[kk][1]);
        u0[1][kk] = -2.f * cck[kk][0] * xvB.x;
        u1[1][kk] = -2.f * cck[kk][1] * xvB.y;
    }

    // hoisted smem pointers: subslice s adds s*8*ZROW (B) / s*16 (gmeta)
    const u32*    zb_b  = smem + r * ZROW + q * 16;
    const float4* zb_gm = (const float4*)(smem + 32 * ZROW) + 2 * r;
    const float4* zb_bb = (const float4*)(smem + 32 * ZROW + 256);

    float c[2][16][4];    // [kk][j][frag]
#pragma unroll
    for (int kk = 0; kk < 2; ++kk)
#pragma unroll
        for (int j = 0; j < 16; ++j) {
            c[kk][j][0] = 0.f; c[kk][j][1] = 0.f; c[kk][j][2] = 0.f; c[kk][j][3] = 0.f;
        }

    const char* gsrc = gtiles + (size_t)tid * 16;

    // prologue: 18 segs x 1024B stride (64 threads)
#pragma unroll
    for (int i = 0; i < 18; ++i)
        asm volatile("cp.async.cg.shared.global [%0], [%1], 16;"
                     :: "r"(sbase + tid * 16 + i * 1024), "l"(gsrc + i * 1024) : "memory");
    asm volatile("cp.async.commit_group;" ::: "memory");
    gsrc += TILE_BYTES;

#pragma unroll 1
    for (int gc = 0; gc < NCHUNK; gc += 2) {
#pragma unroll
        for (int st = 0; st < 2; ++st) {
            asm volatile("cp.async.wait_group 0;" ::: "memory");
            __syncthreads();
            if (gc + 1 + st < NCHUNK) {
                const u32 dstb = sbase + (1 - st) * TILE_BYTES + tid * 16;
#pragma unroll
                for (int i = 0; i < 18; ++i)
                    asm volatile("cp.async.cg.shared.global [%0], [%1], 16;"
                                 :: "r"(dstb + i * 1024), "l"(gsrc + i * 1024) : "memory");
                asm volatile("cp.async.commit_group;" ::: "memory");
            }
            gsrc += TILE_BYTES;

            // 4 subslices (16 g each); skips warp-uniform, mh-warps near-agree
            const float4* bb = zb_bb + st * (TILE_U32 / 4);
            const u32*    bs = zb_b  + st * TILE_U32;
            const float4* gs = zb_gm + st * (TILE_U32 / 4);
#pragma unroll
            for (int s = 0; s < 4; ++s) {
                float4 bx = bb[s];
                float dx = fmaxf(0.f, fmaxf(bx.x - tmxx, tmnx - bx.y));
                float dy = fmaxf(0.f, fmaxf(bx.z - tmxy, tmny - bx.w));
                float d0 = dx * dx, d1 = dy * dy;
                bool sk0 = fmaf(d0, cck[0][0], d1 * cck[0][1]) < SKIP_THR;
                bool sk1 = fmaf(d0, cck[1][0], d1 * cck[1][1]) < SKIP_THR;
                do_sub(bs + s * 8 * ZROW, gs + s * 16, sk0, sk1, At, u0, u1, c);
            }
        }
    }

    // ---- epilogue: direct store, warp owns 16 rows x full z -------------------
    float* oA = out_all + ((size_t)b * NT + pA) * (DZ * 2);
    float* oB = out_all + ((size_t)b * NT + pB) * (DZ * 2);
#pragma unroll
    for (int j = 0; j < 16; ++j) {
        int n0 = 16 * j + 4 * r;    // z-pair (8j+2r, +1), k-interleaved
        *(float4*)(oA + n0) = make_float4(c[0][j][0], c[1][j][0],
                                          c[0][j][1], c[1][j][1]);
        *(float4*)(oB + n0) = make_float4(c[0][j][2], c[1][j][2],
                                          c[0][j][3], c[1][j][3]);
    }
}

extern "C" void kernel_launch(void* const* d_in, const int* in_sizes, int n_in,
                              void* d_out, int out_size)
{
    const float* xg  = (const float*)d_in[0];   // (4,64,64,2)
    const float* zg  = (const float*)d_in[1];   // (4,64,64,128)
    const float* xt  = (const float*)d_in[2];   // (4,2048,2)
    const float* lsp = (const float*)d_in[3];   // (2,2)
    float* out = (float*)d_out;                 // (4,2048,256)

    rank_pts<<<NB * 80, RT>>>(xt, xg);
    scatter_perm<<<NB * 6144 / RT, RT>>>();
    prep_tiles<<<NB * NCHUNK, PTHREADS>>>(zg, xg, lsp);
    setconv_h<<<NB * (NT / MT), NTHREADS>>>(xt, lsp, out);
}

// round 16
// speedup vs baseline: 1.5592x; 1.5592x over previous
#include <cuda_runtime.h>
#include <cuda_fp16.h>
#include <cstdint>

// Shapes (fixed)
#define NB 4
#define NG 4096
#define DZ 128
#define NT 2048

// Tiling
#define MT 32              // t rows per CTA (2 m16 tiles per warp)
#define GC 128             // g per chunk (doubled vs R8: halves barrier count)
#define NCHUNK (NG/GC)     // 32
#define ZROW 132           // u32 stride per g-pair row (pad 4 -> conflict-free)
#define GMETA_OFF (64*ZROW)         // 8448 u32
#define TILE_U32 9216               // 8448 B-region + 512 gmeta + pad
#define TILE_BYTES (TILE_U32*4)     // 36864 = 128 thr * 18 * 16B exactly
#define NTHREADS 128       // 4 warps: 2 kk x 2 gs
#define PTHREADS 256
#define SMEM_BYTES (2*TILE_BYTES)   // 73728 (dynamic; needs attribute)

typedef unsigned int u32;

// Pre-packed tiles: [b][chunk][ Z f16x2 64xZROW | gmeta 128 x {xg0,xg1,Bg0,Bg1} | pad ]
__device__ __align__(16) u32 g_Zh[(size_t)NB * NCHUNK * TILE_U32];

__device__ __forceinline__ float ex2f(float x) {
    float y; asm("ex2.approx.f32 %0, %1;" : "=f"(y) : "f"(x)); return y;
}
__device__ __forceinline__ u32 f16x2(float lo, float hi) {
    u32 d; asm("cvt.rn.f16x2.f32 %0, %1, %2;" : "=r"(d) : "f"(hi), "f"(lo)); return d;
}
__device__ __forceinline__ u32 smem_u32(const void* p) {
    u32 a;
    asm("{ .reg .u64 t; cvta.to.shared.u64 t, %1; cvt.u32.u64 %0, t; }" : "=r"(a) : "l"(p));
    return a;
}
// non-volatile: register deps give correctness; ptxas schedules freely
__device__ __forceinline__ void mma16816(float* c, u32 a0, u32 a1, u32 a2, u32 a3,
                                         u32 b0, u32 b1) {
    asm("mma.sync.aligned.m16n8k16.row.col.f32.f16.f16.f32 "
        "{%0,%1,%2,%3}, {%4,%5,%6,%7}, {%8,%9}, {%0,%1,%2,%3};"
        : "+f"(c[0]), "+f"(c[1]), "+f"(c[2]), "+f"(c[3])
        : "r"(a0), "r"(a1), "r"(a2), "r"(a3), "r"(b0), "r"(b1));
}
__device__ __forceinline__ void softplus_cc(const float* lsp, int kk, float& c0, float& c1) {
    const float HL2E = 0.7213475204444817f;
    float p0 = lsp[0 * 2 + kk], p1 = lsp[1 * 2 + kk];
    float sp0 = (p0 > 20.f) ? p0 : log1pf(expf(p0));
    float sp1 = (p1 > 20.f) ? p1 : log1pf(expf(p1));
    float i0 = 1.f / (1e-5f + sp0), i1 = 1.f / (1e-5f + sp1);
    c0 = -HL2E * i0 * i0;
    c1 = -HL2E * i1 * i1;
}

// ---------------- prep: pack Z (f16x2, g-pairs, j-permuted) + gmeta ----------
__global__ void __launch_bounds__(PTHREADS)
prep_tiles(const float* __restrict__ zg_all, const float* __restrict__ xg_all,
           const float* __restrict__ lsp)
{
    const int bc  = blockIdx.x;          // b*NCHUNK + chunk  (NB*32 blocks)
    const int b   = bc >> 5;
    const int gc  = bc & 31;
    const int tid = threadIdx.x;
    const int w   = tid >> 5;
    const int z4  = tid & 31;

    u32* tile = g_Zh + (size_t)bc * TILE_U32;
    const float* zbase = zg_all + ((size_t)b * NG + gc * GC) * DZ;

#pragma unroll
    for (int it = 0; it < 8; ++it) {
        int gp = w + it * 8;             // 0..63 (g-pair)
        float4 v0 = __ldg((const float4*)(zbase + (size_t)(2 * gp)     * DZ) + z4);
        float4 v1 = __ldg((const float4*)(zbase + (size_t)(2 * gp + 1) * DZ) + z4);
        u32* dst = tile + gp * ZROW;
        int p0 = (z4 & 1) * 64 + (z4 >> 1);     // perm p(z)=(z&7)*16+(z>>3)
        dst[p0]      = f16x2(v0.x, v1.x);
        dst[p0 + 16] = f16x2(v0.y, v1.y);
        dst[p0 + 32] = f16x2(v0.z, v1.z);
        dst[p0 + 48] = f16x2(v0.w, v1.w);
    }

    // gmeta: per g {xg0, xg1, Bg_k0, Bg_k1}, Bg_k = ck0*xg0^2 + ck1*xg1^2
    if (tid < GC) {
        float c00, c01, c10, c11;
        softplus_cc(lsp, 0, c00, c01);
        softplus_cc(lsp, 1, c10, c11);
        float2 xgv = __ldg((const float2*)xg_all + (size_t)b * NG + gc * GC + tid);
        float s0 = xgv.x * xgv.x, s1 = xgv.y * xgv.y;
        float Bg0 = fmaf(s0, c00, s1 * c01);
        float Bg1 = fmaf(s0, c10, s1 * c11);
        ((float4*)(tile + GMETA_OFF))[tid] = make_float4(xgv.x, xgv.y, Bg0, Bg1);
    }
}

// -------- per-16g-slice compute: B loaded once, reused by 2 M-tiles ----------
__device__ __forceinline__ void do_slice(
    const u32* bu, const float4* gm,
    int kk, const float* At, const float* u0, const float* u1,
    float (&c)[2][16][4])
{
    const uint4* bup = (const uint4*)bu;
    const uint4* blp = bup + ZROW;    // +4*ZROW u32
    uint4 BU[4], BL[4];
#pragma unroll
    for (int m = 0; m < 4; ++m) { BU[m] = bup[m]; BL[m] = blp[m]; }

    float4 m0 = gm[0], m1 = gm[1], m2 = gm[8], m3 = gm[9];
    float B0 = kk ? m0.w : m0.z;
    float B1 = kk ? m1.w : m1.z;
    float B2 = kk ? m2.w : m2.z;
    float B3 = kk ? m3.w : m3.z;

    // weights for 4 rows x 4 g-cols
    float wv[4][4];
#pragma unroll
    for (int rr = 0; rr < 4; ++rr) {
        wv[rr][0] = ex2f(fmaf(m0.x, u0[rr], fmaf(m0.y, u1[rr], B0)) + At[rr]);
        wv[rr][1] = ex2f(fmaf(m1.x, u0[rr], fmaf(m1.y, u1[rr], B1)) + At[rr]);
        wv[rr][2] = ex2f(fmaf(m2.x, u0[rr], fmaf(m2.y, u1[rr], B2)) + At[rr]);
        wv[rr][3] = ex2f(fmaf(m3.x, u0[rr], fmaf(m3.y, u1[rr], B3)) + At[rr]);
    }
    u32 a[2][4];
#pragma unroll
    for (int m = 0; m < 2; ++m) {
        a[m][0] = f16x2(wv[2*m][0],   wv[2*m][1]);
        a[m][1] = f16x2(wv[2*m+1][0], wv[2*m+1][1]);
        a[m][2] = f16x2(wv[2*m][2],   wv[2*m][3]);
        a[m][3] = f16x2(wv[2*m+1][2], wv[2*m+1][3]);
    }
#pragma unroll
    for (int j = 0; j < 16; ++j) {
        u32 b0 = ((const u32*)BU)[j];
        u32 b1 = ((const u32*)BL)[j];
#pragma unroll
        for (int m = 0; m < 2; ++m)
            mma16816(c[m][j], a[m][0], a[m][1], a[m][2], a[m][3], b0, b1);
    }
}

// ---------------- main: factored weights + HMMA, cp.async double buffer ------
__global__ void __launch_bounds__(NTHREADS, 2)
setconv_h(const float* __restrict__ xt_all,
          const float* __restrict__ lsp,
          float* __restrict__ out_all)
{
    extern __shared__ __align__(16) u32 smem[];   // 2 * TILE_U32

    const int cta  = blockIdx.x;        // 256 CTAs
    const int b    = cta >> 6;
    const int t0   = (cta & 63) * MT;
    const int tid  = threadIdx.x;
    const int w    = tid >> 5;          // 0..3
    const int lane = tid & 31;
    const int kk   = w >> 1;            // RBF kernel index
    const int gs   = w & 1;             // g-split half (4 slices each)
    const int q    = lane >> 2;         // 0..7
    const int r    = lane & 3;          // 0..3

    const u32 sbase = smem_u32(smem);
    const char* gtiles = (const char*)(g_Zh + (size_t)b * NCHUNK * TILE_U32);

    // RBF coefficients for this warp's k
    float cc0, cc1;
    softplus_cc(lsp, kk, cc0, cc1);

    // 4 rows: [0]=t0+q, [1]=t0+8+q (tile0); [2]=t0+16+q, [3]=t0+24+q (tile1)
    float At[4], u0[4], u1[4];
#pragma unroll
    for (int rr = 0; rr < 4; ++rr) {
        float2 xv = ((const float2*)xt_all)[(size_t)b * NT + t0 + rr * 8 + q];
        At[rr] = fmaf(xv.x * xv.x, cc0, xv.y * xv.y * cc1);
        u0[rr] = -2.f * cc0 * xv.x;
        u1[rr] = -2.f * cc1 * xv.y;
    }

    // hoisted smem offsets (stage 0); warp's slices: s = gs + 2i, i=0..3
    const u32*    zb_bu = smem + (gs * 8 + r) * ZROW + q * 16;
    const float4* zb_gm = (const float4*)(smem + GMETA_OFF) + gs * 16 + 2 * r;

    float c[2][16][4];
#pragma unroll
    for (int m = 0; m < 2; ++m)
#pragma unroll
        for (int j = 0; j < 16; ++j) {
            c[m][j][0] = 0.f; c[m][j][1] = 0.f; c[m][j][2] = 0.f; c[m][j][3] = 0.f;
        }

    const char* gsrc = gtiles + (size_t)tid * 16;   // chunk 0 src base

    // prologue: stage chunk 0 into stage 0 (18 segs x 2048B stride)
#pragma unroll
    for (int i = 0; i < 18; ++i)
        asm volatile("cp.async.cg.shared.global [%0], [%1], 16;"
                     :: "r"(sbase + tid * 16 + i * 2048), "l"(gsrc + i * 2048) : "memory");
    asm volatile("cp.async.commit_group;" ::: "memory");
    gsrc += TILE_BYTES;

#pragma unroll 1
    for (int gc = 0; gc < NCHUNK; gc += 2) {
#pragma unroll
        for (int st = 0; st < 2; ++st) {
            asm volatile("cp.async.wait_group 0;" ::: "memory");
            __syncthreads();
            if (gc + 1 + st < NCHUNK) {
                const u32 dstb = sbase + (1 - st) * TILE_BYTES + tid * 16;
#pragma unroll
                for (int i = 0; i < 18; ++i)
                    asm volatile("cp.async.cg.shared.global [%0], [%1], 16;"
                                 :: "r"(dstb + i * 2048), "l"(gsrc + i * 2048) : "memory");
                asm volatile("cp.async.commit_group;" ::: "memory");
            }
            gsrc += TILE_BYTES;

            const u32*    bs = zb_bu + st * TILE_U32;
            const float4* gm = zb_gm + st * (TILE_U32 / 4);
#pragma unroll
            for (int i = 0; i < 4; ++i)
                do_slice(bs + i * 16 * ZROW, gm + i * 32, kk, At, u0, u1, c);
        }
    }

    // ---- reduce g-split pairs via smem, then store ----
    __syncthreads();
    float4* red = (float4*)smem;       // 32KB needed <= 73728 available
    if (gs == 1) {
#pragma unroll
        for (int m = 0; m < 2; ++m)
#pragma unroll
            for (int j = 0; j < 16; ++j)
                red[((kk * 2 + m) * 16 + j) * 32 + lane] =
                    make_float4(c[m][j][0], c[m][j][1], c[m][j][2], c[m][j][3]);
    }
    __syncthreads();
    if (gs == 0) {
#pragma unroll
        for (int m = 0; m < 2; ++m) {
            float* oA = out_all + ((size_t)b * NT + t0 + m * 16 + q) * (DZ * 2) + kk;
            float* oB = oA + 8 * (DZ * 2);
#pragma unroll
            for (int j = 0; j < 16; ++j) {
                float4 v = red[((kk * 2 + m) * 16 + j) * 32 + lane];
                int n0 = 16 * j + 4 * r;
                oA[n0]     = c[m][j][0] + v.x;
                oA[n0 + 2] = c[m][j][1] + v.y;
                oB[n0]     = c[m][j][2] + v.z;
                oB[n0 + 2] = c[m][j][3] + v.w;
            }
        }
    }
}

extern "C" void kernel_launch(void* const* d_in, const int* in_sizes, int n_in,
                              void* d_out, int out_size)
{
    const float* xg  = (const float*)d_in[0];   // (4,64,64,2)
    const float* zg  = (const float*)d_in[1];   // (4,64,64,128)
    const float* xt  = (const float*)d_in[2];   // (4,2048,2)
    const float* lsp = (const float*)d_in[3];   // (2,2)
    float* out = (float*)d_out;                 // (4,2048,256)

    cudaFuncSetAttribute(setconv_h,
                         cudaFuncAttributeMaxDynamicSharedMemorySize, SMEM_BYTES);

    prep_tiles<<<NB * NCHUNK, PTHREADS>>>(zg, xg, lsp);
    setconv_h<<<NB * (NT / MT), NTHREADS, SMEM_BYTES>>>(xt, lsp, out);
}

// round 17
// speedup vs baseline: 1.5644x; 1.0034x over previous
#include <cuda_runtime.h>
#include <cuda_fp16.h>
#include <cstdint>

// Shapes (fixed)
#define NB 4
#define NG 4096
#define DZ 128
#define NT 2048

// Tiling
#define MT 32              // t rows per CTA (2 m16 tiles per warp)
#define GC 128             // g per chunk (32 chunks -> 32 barriers)
#define NCHUNK (NG/GC)     // 32
#define ZROW 132           // u32 stride per g-pair row (pad 4 -> conflict-free)
#define GMETA_OFF (64*ZROW)         // 8448 u32
#define TILE_U32 9216               // 8448 B-region + 512 gmeta + pad
#define TILE_BYTES (TILE_U32*4)     // 36864 = 128 thr * 18 * 16B exactly
#define NTHREADS 128       // 4 warps: 2 kk x 2 gs
#define PTHREADS 256
#define SMEM_BYTES (2*TILE_BYTES)   // 73728 (dynamic; needs attribute)

typedef unsigned int u32;

// Pre-packed tiles: [b][chunk][ Z f16x2 64xZROW | gmeta 128 x {xg0,xg1,Bg0,Bg1} | pad ]
__device__ __align__(16) u32 g_Zh[(size_t)NB * NCHUNK * TILE_U32];

__device__ __forceinline__ float ex2f(float x) {
    float y; asm("ex2.approx.f32 %0, %1;" : "=f"(y) : "f"(x)); return y;
}
__device__ __forceinline__ u32 f16x2(float lo, float hi) {
    u32 d; asm("cvt.rn.f16x2.f32 %0, %1, %2;" : "=r"(d) : "f"(hi), "f"(lo)); return d;
}
__device__ __forceinline__ u32 smem_u32(const void* p) {
    u32 a;
    asm("{ .reg .u64 t; cvta.to.shared.u64 t, %1; cvt.u32.u64 %0, t; }" : "=r"(a) : "l"(p));
    return a;
}
// non-volatile: register deps give correctness; ptxas schedules freely
__device__ __forceinline__ void mma16816(float* c, u32 a0, u32 a1, u32 a2, u32 a3,
                                         u32 b0, u32 b1) {
    asm("mma.sync.aligned.m16n8k16.row.col.f32.f16.f16.f32 "
        "{%0,%1,%2,%3}, {%4,%5,%6,%7}, {%8,%9}, {%0,%1,%2,%3};"
        : "+f"(c[0]), "+f"(c[1]), "+f"(c[2]), "+f"(c[3])
        : "r"(a0), "r"(a1), "r"(a2), "r"(a3), "r"(b0), "r"(b1));
}
__device__ __forceinline__ void softplus_cc(const float* lsp, int kk, float& c0, float& c1) {
    const float HL2E = 0.7213475204444817f;
    float p0 = lsp[0 * 2 + kk], p1 = lsp[1 * 2 + kk];
    float sp0 = (p0 > 20.f) ? p0 : log1pf(expf(p0));
    float sp1 = (p1 > 20.f) ? p1 : log1pf(expf(p1));
    float i0 = 1.f / (1e-5f + sp0), i1 = 1.f / (1e-5f + sp1);
    c0 = -HL2E * i0 * i0;
    c1 = -HL2E * i1 * i1;
}

// ---------------- prep: pack Z (f16x2, g-pairs, j-permuted) + gmeta ----------
// 256 blocks: each handles HALF a chunk (32 g-pairs) -> covers all 148 SMs.
__global__ void __launch_bounds__(PTHREADS)
prep_tiles(const float* __restrict__ zg_all, const float* __restrict__ xg_all,
           const float* __restrict__ lsp)
{
    const int blk  = blockIdx.x;         // (b*NCHUNK + chunk)*2 + half  (NB*64 blocks)
    const int bc   = blk >> 1;
    const int half = blk & 1;
    const int b    = bc >> 5;
    const int gc   = bc & 31;
    const int tid = threadIdx.x;
    const int w   = tid >> 5;
    const int z4  = tid & 31;

    u32* tile = g_Zh + (size_t)bc * TILE_U32;
    const float* zbase = zg_all + ((size_t)b * NG + gc * GC) * DZ;

#pragma unroll
    for (int it = 0; it < 4; ++it) {
        int gp = half * 32 + w + it * 8;     // this block's 32 g-pairs
        float4 v0 = __ldg((const float4*)(zbase + (size_t)(2 * gp)     * DZ) + z4);
        float4 v1 = __ldg((const float4*)(zbase + (size_t)(2 * gp + 1) * DZ) + z4);
        u32* dst = tile + gp * ZROW;
        int p0 = (z4 & 1) * 64 + (z4 >> 1);  // perm p(z)=(z&7)*16+(z>>3)
        dst[p0]      = f16x2(v0.x, v1.x);
        dst[p0 + 16] = f16x2(v0.y, v1.y);
        dst[p0 + 32] = f16x2(v0.z, v1.z);
        dst[p0 + 48] = f16x2(v0.w, v1.w);
    }

    // gmeta: per g {xg0, xg1, Bg_k0, Bg_k1}, Bg_k = ck0*xg0^2 + ck1*xg1^2
    if (tid < 64) {
        int gl = half * 64 + tid;            // this block's 64 g
        float c00, c01, c10, c11;
        softplus_cc(lsp, 0, c00, c01);
        softplus_cc(lsp, 1, c10, c11);
        float2 xgv = __ldg((const float2*)xg_all + (size_t)b * NG + gc * GC + gl);
        float s0 = xgv.x * xgv.x, s1 = xgv.y * xgv.y;
        float Bg0 = fmaf(s0, c00, s1 * c01);
        float Bg1 = fmaf(s0, c10, s1 * c11);
        ((float4*)(tile + GMETA_OFF))[gl] = make_float4(xgv.x, xgv.y, Bg0, Bg1);
    }
}

// -------- per-16g-slice compute: B loaded once, reused by 2 M-tiles ----------
__device__ __forceinline__ void do_slice(
    const u32* bu, const float4* gm,
    int kk, const float* At, const float* u0, const float* u1,
    float (&c)[2][16][4])
{
    const uint4* bup = (const uint4*)bu;
    const uint4* blp = bup + ZROW;    // +4*ZROW u32
    uint4 BU[4], BL[4];
#pragma unroll
    for (int m = 0; m < 4; ++m) { BU[m] = bup[m]; BL[m] = blp[m]; }

    float4 m0 = gm[0], m1 = gm[1], m2 = gm[8], m3 = gm[9];
    float B0 = kk ? m0.w : m0.z;
    float B1 = kk ? m1.w : m1.z;
    float B2 = kk ? m2.w : m2.z;
    float B3 = kk ? m3.w : m3.z;

    // weights for 4 rows x 4 g-cols
    float wv[4][4];
#pragma unroll
    for (int rr = 0; rr < 4; ++rr) {
        wv[rr][0] = ex2f(fmaf(m0.x, u0[rr], fmaf(m0.y, u1[rr], B0)) + At[rr]);
        wv[rr][1] = ex2f(fmaf(m1.x, u0[rr], fmaf(m1.y, u1[rr], B1)) + At[rr]);
        wv[rr][2] = ex2f(fmaf(m2.x, u0[rr], fmaf(m2.y, u1[rr], B2)) + At[rr]);
        wv[rr][3] = ex2f(fmaf(m3.x, u0[rr], fmaf(m3.y, u1[rr], B3)) + At[rr]);
    }
    u32 a[2][4];
#pragma unroll
    for (int m = 0; m < 2; ++m) {
        a[m][0] = f16x2(wv[2*m][0],   wv[2*m][1]);
        a[m][1] = f16x2(wv[2*m+1][0], wv[2*m+1][1]);
        a[m][2] = f16x2(wv[2*m][2],   wv[2*m][3]);
        a[m][3] = f16x2(wv[2*m+1][2], wv[2*m+1][3]);
    }
#pragma unroll
    for (int j = 0; j < 16; ++j) {
        u32 b0 = ((const u32*)BU)[j];
        u32 b1 = ((const u32*)BL)[j];
#pragma unroll
        for (int m = 0; m < 2; ++m)
            mma16816(c[m][j], a[m][0], a[m][1], a[m][2], a[m][3], b0, b1);
    }
}

// ---------------- main: factored weights + HMMA, cp.async double buffer ------
__global__ void __launch_bounds__(NTHREADS, 2)
setconv_h(const float* __restrict__ xt_all,
          const float* __restrict__ lsp,
          float* __restrict__ out_all)
{
    extern __shared__ __align__(16) u32 smem[];   // 2 * TILE_U32

    const int cta  = blockIdx.x;        // 256 CTAs
    const int b    = cta >> 6;
    const int t0   = (cta & 63) * MT;
    const int tid  = threadIdx.x;
    const int w    = tid >> 5;          // 0..3
    const int lane = tid & 31;
    const int kk   = w >> 1;            // RBF kernel index
    const int gs   = w & 1;             // g-split half (4 slices each)
    const int q    = lane >> 2;         // 0..7
    const int r    = lane & 3;          // 0..3

    const u32 sbase = smem_u32(smem);
    const char* gtiles = (const char*)(g_Zh + (size_t)b * NCHUNK * TILE_U32);

    // RBF coefficients for this warp's k
    float cc0, cc1;
    softplus_cc(lsp, kk, cc0, cc1);

    // 4 rows: [0]=t0+q, [1]=t0+8+q (tile0); [2]=t0+16+q, [3]=t0+24+q (tile1)
    float At[4], u0[4], u1[4];
#pragma unroll
    for (int rr = 0; rr < 4; ++rr) {
        float2 xv = ((const float2*)xt_all)[(size_t)b * NT + t0 + rr * 8 + q];
        At[rr] = fmaf(xv.x * xv.x, cc0, xv.y * xv.y * cc1);
        u0[rr] = -2.f * cc0 * xv.x;
        u1[rr] = -2.f * cc1 * xv.y;
    }

    // hoisted smem offsets (stage 0); warp's slices: s = gs + 2i, i=0..3
    const u32*    zb_bu = smem + (gs * 8 + r) * ZROW + q * 16;
    const float4* zb_gm = (const float4*)(smem + GMETA_OFF) + gs * 16 + 2 * r;

    float c[2][16][4];
#pragma unroll
    for (int m = 0; m < 2; ++m)
#pragma unroll
        for (int j = 0; j < 16; ++j) {
            c[m][j][0] = 0.f; c[m][j][1] = 0.f; c[m][j][2] = 0.f; c[m][j][3] = 0.f;
        }

    const char* gsrc = gtiles + (size_t)tid * 16;   // chunk 0 src base

    // prologue: stage chunk 0 into stage 0 (18 segs x 2048B stride)
#pragma unroll
    for (int i = 0; i < 18; ++i)
        asm volatile("cp.async.cg.shared.global [%0], [%1], 16;"
                     :: "r"(sbase + tid * 16 + i * 2048), "l"(gsrc + i * 2048) : "memory");
    asm volatile("cp.async.commit_group;" ::: "memory");
    gsrc += TILE_BYTES;

#pragma unroll 1
    for (int gc = 0; gc < NCHUNK; gc += 2) {
#pragma unroll
        for (int st = 0; st < 2; ++st) {
            asm volatile("cp.async.wait_group 0;" ::: "memory");
            __syncthreads();
            if (gc + 1 + st < NCHUNK) {
                const u32 dstb = sbase + (1 - st) * TILE_BYTES + tid * 16;
#pragma unroll
                for (int i = 0; i < 18; ++i)
                    asm volatile("cp.async.cg.shared.global [%0], [%1], 16;"
                                 :: "r"(dstb + i * 2048), "l"(gsrc + i * 2048) : "memory");
                asm volatile("cp.async.commit_group;" ::: "memory");
            }
            gsrc += TILE_BYTES;

            const u32*    bs = zb_bu + st * TILE_U32;
            const float4* gm = zb_gm + st * (TILE_U32 / 4);
#pragma unroll
            for (int i = 0; i < 4; ++i)
                do_slice(bs + i * 16 * ZROW, gm + i * 32, kk, At, u0, u1, c);
        }
    }

    // ---- reduce g-split pairs via smem, then store ----
    __syncthreads();
    float4* red = (float4*)smem;       // 32KB needed <= 73728 available
    if (gs == 1) {
#pragma unroll
        for (int m = 0; m < 2; ++m)
#pragma unroll
            for (int j = 0; j < 16; ++j)
                red[((kk * 2 + m) * 16 + j) * 32 + lane] =
                    make_float4(c[m][j][0], c[m][j][1], c[m][j][2], c[m][j][3]);
    }
    __syncthreads();
    if (gs == 0) {
#pragma unroll
        for (int m = 0; m < 2; ++m) {
            float* oA = out_all + ((size_t)b * NT + t0 + m * 16 + q) * (DZ * 2) + kk;
            float* oB = oA + 8 * (DZ * 2);
#pragma unroll
            for (int j = 0; j < 16; ++j) {
                float4 v = red[((kk * 2 + m) * 16 + j) * 32 + lane];
                int n0 = 16 * j + 4 * r;
                oA[n0]     = c[m][j][0] + v.x;
                oA[n0 + 2] = c[m][j][1] + v.y;
                oB[n0]     = c[m][j][2] + v.z;
                oB[n0 + 2] = c[m][j][3] + v.w;
            }
        }
    }
}

extern "C" void kernel_launch(void* const* d_in, const int* in_sizes, int n_in,
                              void* d_out, int out_size)
{
    const float* xg  = (const float*)d_in[0];   // (4,64,64,2)
    const float* zg  = (const float*)d_in[1];   // (4,64,64,128)
    const float* xt  = (const float*)d_in[2];   // (4,2048,2)
    const float* lsp = (const float*)d_in[3];   // (2,2)
    float* out = (float*)d_out;                 // (4,2048,256)

    cudaFuncSetAttribute(setconv_h,
                         cudaFuncAttributeMaxDynamicSharedMemorySize, SMEM_BYTES);

    prep_tiles<<<NB * NCHUNK * 2, PTHREADS>>>(zg, xg, lsp);
    setconv_h<<<NB * (NT / MT), NTHREADS, SMEM_BYTES>>>(xt, lsp, out);
}